// round 11
// baseline (speedup 1.0000x reference)
#include <cuda_runtime.h>
#include <cuda_bf16.h>
#include <cstdint>

#define NN 100000
#define EE 1600000
#define DD 128
#define NBLK ((NN + 1023) / 1024)

// ---------------- scratch (device globals; no allocs allowed) ----------------
__device__ float g_msg[(size_t)NN * DD];     // mean-aggregated messages
__device__ float g_h  [(size_t)NN * DD];     // layer-0 activations
__device__ int   g_rowptr[NN + 1];
__device__ int   g_colidx[EE];
__device__ int   g_hist[NN];
__device__ int   g_bsum[NBLK];
__device__ int   g_ei_is64;

// ---------------- f32x2 helpers (FFMA2 path, PTX-only) ----------------
__device__ __forceinline__ double ffma2(double a, double b, double c) {
    double d;
    asm("fma.rn.f32x2 %0, %1, %2, %3;" : "=d"(d) : "d"(a), "d"(b), "d"(c));
    return d;
}
__device__ __forceinline__ double pk2(float lo, float hi) {
    double d;
    asm("mov.b64 %0, {%1, %2};" : "=d"(d) : "f"(lo), "f"(hi));
    return d;
}
__device__ __forceinline__ float fold2(double d) {
    float x, y;
    asm("mov.b64 {%0, %1}, %2;" : "=f"(x), "=f"(y) : "d"(d));
    return x + y;
}

// ---------------- edge-index dtype detection ----------------
__global__ void detect_kernel(const int* __restrict__ ei_words) {
    if (threadIdx.x == 0 && blockIdx.x == 0) {
        int is64 = 1;
        for (int i = 1; i < 256; i += 2) {
            if (ei_words[i] != 0) { is64 = 0; break; }
        }
        g_ei_is64 = is64;
    }
}
__device__ __forceinline__ int load_edge(const void* ei, size_t idx) {
    if (g_ei_is64) return (int)((const long long*)ei)[idx];
    return ((const int*)ei)[idx];
}

// ---------------- CSR build ----------------
__global__ void zero_hist_kernel(int N) {
    int i = blockIdx.x * blockDim.x + threadIdx.x;
    if (i < N) g_hist[i] = 0;
}
__global__ void hist_kernel(const void* __restrict__ ei, int E) {
    int e = blockIdx.x * blockDim.x + threadIdx.x;
    if (e >= E) return;
    atomicAdd(&g_hist[load_edge(ei, (size_t)E + e)], 1);
}
__global__ __launch_bounds__(1024)
void scan1_kernel(int N) {
    __shared__ int s[1024];
    int gi = blockIdx.x * 1024 + threadIdx.x;
    int v = (gi < N) ? g_hist[gi] : 0;
    s[threadIdx.x] = v;
    __syncthreads();
    int x = v;
#pragma unroll
    for (int off = 1; off < 1024; off <<= 1) {
        int t = (threadIdx.x >= off) ? s[threadIdx.x - off] : 0;
        __syncthreads();
        x += t;
        s[threadIdx.x] = x;
        __syncthreads();
    }
    if (gi <= N) g_rowptr[gi] = x - v;
    if (threadIdx.x == 1023) g_bsum[blockIdx.x] = x;
}
__global__ void scan2_kernel(int nblk) {
    if (threadIdx.x == 0 && blockIdx.x == 0) {
        int run = 0;
        for (int b = 0; b < nblk; b++) { int t = g_bsum[b]; g_bsum[b] = run; run += t; }
    }
}
__global__ void scan3_kernel(int N, int E) {
    int i = blockIdx.x * blockDim.x + threadIdx.x;
    if (i < N) {
        g_rowptr[i] += g_bsum[i >> 10];
        g_hist[i] = 0;
    }
    if (i == 0) g_rowptr[N] = E;
}
__global__ void scatter_kernel(const void* __restrict__ ei, int E) {
    int e = blockIdx.x * blockDim.x + threadIdx.x;
    if (e >= E) return;
    int s = load_edge(ei, e);
    int d = load_edge(ei, (size_t)E + e);
    int p = g_rowptr[d] + atomicAdd(&g_hist[d], 1);
    g_colidx[p] = s;
}

// ---------------- gather aggregation: one warp per dst node ----------------
__global__ __launch_bounds__(256)
void gather_agg_kernel(const float* __restrict__ feat_in, int N) {
    const float* feat = feat_in ? feat_in : g_h;
    int node = (blockIdx.x * blockDim.x + threadIdx.x) >> 5;
    int lane = threadIdx.x & 31;
    if (node >= N) return;

    int beg = g_rowptr[node];
    int end = g_rowptr[node + 1];
    const float4* f4 = reinterpret_cast<const float4*>(feat);
    float4 acc = make_float4(0.f, 0.f, 0.f, 0.f);

    int e = beg;
    for (; e + 4 <= end; e += 4) {
        int s0 = g_colidx[e], s1 = g_colidx[e + 1], s2 = g_colidx[e + 2], s3 = g_colidx[e + 3];
        float4 a = f4[(size_t)s0 * 32 + lane];
        float4 b = f4[(size_t)s1 * 32 + lane];
        float4 c = f4[(size_t)s2 * 32 + lane];
        float4 d = f4[(size_t)s3 * 32 + lane];
        acc.x += (a.x + b.x) + (c.x + d.x);
        acc.y += (a.y + b.y) + (c.y + d.y);
        acc.z += (a.z + b.z) + (c.z + d.z);
        acc.w += (a.w + b.w) + (c.w + d.w);
    }
    for (; e < end; e++) {
        float4 a = f4[(size_t)g_colidx[e] * 32 + lane];
        acc.x += a.x; acc.y += a.y; acc.z += a.z; acc.w += a.w;
    }
    float r = 1.f / fmaxf((float)(end - beg), 1.f);
    acc.x *= r; acc.y *= r; acc.z *= r; acc.w *= r;
    reinterpret_cast<float4*>(g_msg)[(size_t)node * 32 + lane] = acc;
}

// ---------------- fused SAGE layer GEMM (f32x2 FFMA2, unconstrained regs) ----------------
// OUT[n][c] = act( sum_k g_msg[n][k]*Wl[k][c] + X[n][k]*Wr[k][c] + B[c] )
// Tiling identical to the 739us baseline: BM=64, BN=128, BK=16, 256 thr, 8x4 microtile.
// K SIMD-ized in pairs: lo lane = even k, hi lane = odd k; folded at the end.
#define S_BM 64
#define S_BK 16
template <bool RELU>
__global__ __launch_bounds__(256)
void sage_kernel(const float* __restrict__ X_in,
                 const float* __restrict__ Wl,
                 const float* __restrict__ Wr,
                 const float* __restrict__ B,
                 float* __restrict__ OUT_in,
                 int N) {
    const float* X = X_in ? X_in : g_h;
    float* OUT     = OUT_in ? OUT_in : g_h;

    __shared__ __align__(16) float sAx[S_BM][S_BK];
    __shared__ __align__(16) float sAm[S_BM][S_BK];
    __shared__ __align__(16) float sBl[S_BK][128];
    __shared__ __align__(16) float sBr[S_BK][128];

    const int tid = threadIdx.x;
    const int tx  = tid & 31;
    const int ty  = tid >> 5;
    const int bm  = blockIdx.x * S_BM;

    double acc2[8][4];
#pragma unroll
    for (int i = 0; i < 8; i++)
#pragma unroll
        for (int j = 0; j < 4; j++) acc2[i][j] = 0.0;   // all-zero bits = {0f,0f}

    for (int kc = 0; kc < DD; kc += S_BK) {
        // A tiles: 64x16 floats each, scalar coalesced loads (identical to baseline)
#pragma unroll
        for (int i = 0; i < 4; i++) {
            int idx = tid + i * 256;
            int r = idx >> 4, c = idx & 15;
            int n = bm + r;
            float vx = 0.f, vm = 0.f;
            if (n < N) {
                vx = X[(size_t)n * DD + kc + c];
                vm = g_msg[(size_t)n * DD + kc + c];
            }
            sAx[r][c] = vx;
            sAm[r][c] = vm;
        }
        // B tiles: 16x128 each
#pragma unroll
        for (int i = 0; i < 8; i++) {
            int idx = tid + i * 256;
            int kk = idx >> 7, c = idx & 127;
            sBl[kk][c] = Wl[(size_t)(kc + kk) * 128 + c];
            sBr[kk][c] = Wr[(size_t)(kc + kk) * 128 + c];
        }
        __syncthreads();

#pragma unroll
        for (int kp = 0; kp < S_BK / 2; kp++) {
            // B rows 2kp, 2kp+1 at cols tx*4..+3; pack per-column k-pairs
            float4 bl0 = *reinterpret_cast<const float4*>(&sBl[2 * kp][tx * 4]);
            float4 bl1 = *reinterpret_cast<const float4*>(&sBl[2 * kp + 1][tx * 4]);
            float4 br0 = *reinterpret_cast<const float4*>(&sBr[2 * kp][tx * 4]);
            float4 br1 = *reinterpret_cast<const float4*>(&sBr[2 * kp + 1][tx * 4]);
            double pbl[4], pbr[4];
            pbl[0] = pk2(bl0.x, bl1.x); pbl[1] = pk2(bl0.y, bl1.y);
            pbl[2] = pk2(bl0.z, bl1.z); pbl[3] = pk2(bl0.w, bl1.w);
            pbr[0] = pk2(br0.x, br1.x); pbr[1] = pk2(br0.y, br1.y);
            pbr[2] = pk2(br0.z, br1.z); pbr[3] = pk2(br0.w, br1.w);
#pragma unroll
            for (int i = 0; i < 8; i++) {
                double am2 = *reinterpret_cast<const double*>(&sAm[ty * 8 + i][kp * 2]);
                double ax2 = *reinterpret_cast<const double*>(&sAx[ty * 8 + i][kp * 2]);
#pragma unroll
                for (int j = 0; j < 4; j++) {
                    acc2[i][j] = ffma2(am2, pbl[j], acc2[i][j]);
                    acc2[i][j] = ffma2(ax2, pbr[j], acc2[i][j]);
                }
            }
        }
        __syncthreads();
    }

    float4 bias = *reinterpret_cast<const float4*>(&B[tx * 4]);
#pragma unroll
    for (int i = 0; i < 8; i++) {
        int n = bm + ty * 8 + i;
        if (n < N) {
            float4 o;
            o.x = fold2(acc2[i][0]) + bias.x;
            o.y = fold2(acc2[i][1]) + bias.y;
            o.z = fold2(acc2[i][2]) + bias.z;
            o.w = fold2(acc2[i][3]) + bias.w;
            if (RELU) {
                o.x = fmaxf(o.x, 0.f); o.y = fmaxf(o.y, 0.f);
                o.z = fmaxf(o.z, 0.f); o.w = fmaxf(o.w, 0.f);
            }
            *reinterpret_cast<float4*>(&OUT[(size_t)n * DD + tx * 4]) = o;
        }
    }
}

// ---------------- fused MLP + pred (unchanged from R9) ----------------
// h1 = relu( relu(EMB) @ Wm1 + bm1 );  PRED[n] = h1[n] . Wm2 + bm2
#define M_BM 32
#define M_BK 32
__global__ __launch_bounds__(256)
void mlp_pred_kernel(const float* __restrict__ EMB,
                     const float* __restrict__ Wm1,
                     const float* __restrict__ bm1,
                     const float* __restrict__ Wm2,
                     const float* __restrict__ bm2,
                     float* __restrict__ PRED,
                     int N) {
    __shared__ float sA[M_BM][M_BK];
    __shared__ float sB[M_BK][256];
    __shared__ float sred[M_BM][65];

    const int tid = threadIdx.x;
    const int tx  = tid & 63;
    const int ty  = tid >> 6;
    const int bm  = blockIdx.x * M_BM;

    float acc[8][4];
#pragma unroll
    for (int i = 0; i < 8; i++)
#pragma unroll
        for (int j = 0; j < 4; j++) acc[i][j] = 0.f;

    for (int kc = 0; kc < DD; kc += M_BK) {
#pragma unroll
        for (int i = 0; i < 4; i++) {
            int idx = tid + i * 256;
            int r = idx >> 5, c = idx & 31;
            int n = bm + r;
            sA[r][c] = (n < N) ? fmaxf(EMB[(size_t)n * DD + kc + c], 0.f) : 0.f;
        }
#pragma unroll
        for (int i = 0; i < 32; i++) {
            int idx = tid + i * 256;
            int kk = idx >> 8, c = idx & 255;
            sB[kk][c] = Wm1[(size_t)(kc + kk) * 256 + c];
        }
        __syncthreads();

#pragma unroll
        for (int kk = 0; kk < M_BK; kk++) {
            float4 b4 = *reinterpret_cast<const float4*>(&sB[kk][tx * 4]);
#pragma unroll
            for (int i = 0; i < 8; i++) {
                float a = sA[ty * 8 + i][kk];
                acc[i][0] += a * b4.x;
                acc[i][1] += a * b4.y;
                acc[i][2] += a * b4.z;
                acc[i][3] += a * b4.w;
            }
        }
        __syncthreads();
    }

    float4 bias = *reinterpret_cast<const float4*>(&bm1[tx * 4]);
    float4 w2   = *reinterpret_cast<const float4*>(&Wm2[tx * 4]);
#pragma unroll
    for (int i = 0; i < 8; i++) {
        float h0 = fmaxf(acc[i][0] + bias.x, 0.f);
        float h1 = fmaxf(acc[i][1] + bias.y, 0.f);
        float h2 = fmaxf(acc[i][2] + bias.z, 0.f);
        float h3 = fmaxf(acc[i][3] + bias.w, 0.f);
        sred[ty * 8 + i][tx] = h0 * w2.x + h1 * w2.y + h2 * w2.z + h3 * w2.w;
    }
    __syncthreads();

    if (tid < M_BM) {
        int n = bm + tid;
        if (n < N) {
            float s = 0.f;
#pragma unroll
            for (int j = 0; j < 64; j++) s += sred[tid][j];
            PRED[n] = s + bm2[0];
        }
    }
}

// ---------------- launcher ----------------
extern "C" void kernel_launch(void* const* d_in, const int* in_sizes, int n_in,
                              void* d_out, int out_size) {
    const float* x   = (const float*)d_in[0];
    const void*  ei  = d_in[1];
    const float* Wl0 = (const float*)d_in[2];
    const float* b0  = (const float*)d_in[3];
    const float* Wr0 = (const float*)d_in[4];
    const float* Wl1 = (const float*)d_in[5];
    const float* b1  = (const float*)d_in[6];
    const float* Wr1 = (const float*)d_in[7];
    const float* Wm1 = (const float*)d_in[8];
    const float* bm1 = (const float*)d_in[9];
    const float* Wm2 = (const float*)d_in[10];
    const float* bm2 = (const float*)d_in[11];

    const int N = in_sizes[0] / DD;
    const int E = in_sizes[1] / 2;

    float* out  = (float*)d_out;
    float* emb  = out;                       // [N,128]
    float* pred = out + (size_t)N * DD;      // [N,1]

    const int egrid = (E + 255) / 256;
    const int ngrid = (N + 255) / 256;
    const int nblk  = (N + 1023) / 1024;
    const int ggrid = (N + 7) / 8;
    const int sgrid = (N + S_BM - 1) / S_BM;
    const int mgrid = (N + M_BM - 1) / M_BM;

    detect_kernel<<<1, 32>>>((const int*)ei);

    // ---- CSR build (once; reused by both layers) ----
    zero_hist_kernel<<<ngrid, 256>>>(N);
    hist_kernel<<<egrid, 256>>>(ei, E);
    scan1_kernel<<<nblk, 1024>>>(N);
    scan2_kernel<<<1, 32>>>(nblk);
    scan3_kernel<<<ngrid, 256>>>(N, E);
    scatter_kernel<<<egrid, 256>>>(ei, E);

    // ---- layer 0 ----
    gather_agg_kernel<<<ggrid, 256>>>(x, N);
    sage_kernel<true><<<sgrid, 256>>>(x, Wl0, Wr0, b0, nullptr, N);   // OUT -> g_h

    // ---- layer 1 (emb -> d_out) ----
    gather_agg_kernel<<<ggrid, 256>>>(nullptr, N);
    sage_kernel<false><<<sgrid, 256>>>(nullptr, Wl1, Wr1, b1, emb, N);

    // ---- post-mp MLP + pred (fused) ----
    mlp_pred_kernel<<<mgrid, 256>>>(emb, Wm1, bm1, Wm2, bm2, pred, N);
}

// round 12
// speedup vs baseline: 1.1912x; 1.1912x over previous
#include <cuda_runtime.h>
#include <cuda_bf16.h>
#include <cstdint>

#define NN 100000
#define EE 1600000
#define DD 128
#define NBLK ((NN + 1023) / 1024)

// ---------------- scratch (device globals; no allocs allowed) ----------------
__device__ float g_msg[(size_t)NN * DD];     // mean-aggregated messages
__device__ float g_h  [(size_t)NN * DD];     // layer-0 activations
__device__ int   g_rowptr[NN + 1];
__device__ int   g_colidx[EE];
__device__ int   g_hist[NN];
__device__ int   g_bsum[NBLK];
__device__ int   g_ei_is64;

// ---------------- edge-index dtype detection ----------------
__global__ void detect_kernel(const int* __restrict__ ei_words) {
    if (threadIdx.x == 0 && blockIdx.x == 0) {
        int is64 = 1;
        for (int i = 1; i < 256; i += 2) {
            if (ei_words[i] != 0) { is64 = 0; break; }
        }
        g_ei_is64 = is64;
    }
}
__device__ __forceinline__ int load_edge(const void* ei, size_t idx) {
    if (g_ei_is64) return (int)((const long long*)ei)[idx];
    return ((const int*)ei)[idx];
}

// ---------------- CSR build ----------------
__global__ void zero_hist_kernel(int N) {
    int i = blockIdx.x * blockDim.x + threadIdx.x;
    if (i < N) g_hist[i] = 0;
}
__global__ void hist_kernel(const void* __restrict__ ei, int E) {
    int e = blockIdx.x * blockDim.x + threadIdx.x;
    if (e >= E) return;
    atomicAdd(&g_hist[load_edge(ei, (size_t)E + e)], 1);
}
__global__ __launch_bounds__(1024)
void scan1_kernel(int N) {
    __shared__ int s[1024];
    int gi = blockIdx.x * 1024 + threadIdx.x;
    int v = (gi < N) ? g_hist[gi] : 0;
    s[threadIdx.x] = v;
    __syncthreads();
    int x = v;
#pragma unroll
    for (int off = 1; off < 1024; off <<= 1) {
        int t = (threadIdx.x >= off) ? s[threadIdx.x - off] : 0;
        __syncthreads();
        x += t;
        s[threadIdx.x] = x;
        __syncthreads();
    }
    if (gi <= N) g_rowptr[gi] = x - v;
    if (threadIdx.x == 1023) g_bsum[blockIdx.x] = x;
}
__global__ void scan2_kernel(int nblk) {
    if (threadIdx.x == 0 && blockIdx.x == 0) {
        int run = 0;
        for (int b = 0; b < nblk; b++) { int t = g_bsum[b]; g_bsum[b] = run; run += t; }
    }
}
__global__ void scan3_kernel(int N, int E) {
    int i = blockIdx.x * blockDim.x + threadIdx.x;
    if (i < N) {
        g_rowptr[i] += g_bsum[i >> 10];
        g_hist[i] = 0;
    }
    if (i == 0) g_rowptr[N] = E;
}
__global__ void scatter_kernel(const void* __restrict__ ei, int E) {
    int e = blockIdx.x * blockDim.x + threadIdx.x;
    if (e >= E) return;
    int s = load_edge(ei, e);
    int d = load_edge(ei, (size_t)E + e);
    int p = g_rowptr[d] + atomicAdd(&g_hist[d], 1);
    g_colidx[p] = s;
}

// ---------------- gather aggregation: one warp per dst node ----------------
__global__ __launch_bounds__(256)
void gather_agg_kernel(const float* __restrict__ feat_in, int N) {
    const float* feat = feat_in ? feat_in : g_h;
    int node = (blockIdx.x * blockDim.x + threadIdx.x) >> 5;
    int lane = threadIdx.x & 31;
    if (node >= N) return;

    int beg = g_rowptr[node];
    int end = g_rowptr[node + 1];
    const float4* f4 = reinterpret_cast<const float4*>(feat);
    float4 acc = make_float4(0.f, 0.f, 0.f, 0.f);

    int e = beg;
    for (; e + 4 <= end; e += 4) {
        int s0 = g_colidx[e], s1 = g_colidx[e + 1], s2 = g_colidx[e + 2], s3 = g_colidx[e + 3];
        float4 a = f4[(size_t)s0 * 32 + lane];
        float4 b = f4[(size_t)s1 * 32 + lane];
        float4 c = f4[(size_t)s2 * 32 + lane];
        float4 d = f4[(size_t)s3 * 32 + lane];
        acc.x += (a.x + b.x) + (c.x + d.x);
        acc.y += (a.y + b.y) + (c.y + d.y);
        acc.z += (a.z + b.z) + (c.z + d.z);
        acc.w += (a.w + b.w) + (c.w + d.w);
    }
    for (; e < end; e++) {
        float4 a = f4[(size_t)g_colidx[e] * 32 + lane];
        acc.x += a.x; acc.y += a.y; acc.z += a.z; acc.w += a.w;
    }
    float r = 1.f / fmaxf((float)(end - beg), 1.f);
    acc.x *= r; acc.y *= r; acc.z *= r; acc.w *= r;
    reinterpret_cast<float4*>(g_msg)[(size_t)node * 32 + lane] = acc;
}

// ---------------- fused SAGE layer GEMM (exact R4 kernel, regs unconstrained) ----------------
// OUT[n][c] = act( sum_k g_msg[n][k]*Wl[k][c] + X[n][k]*Wr[k][c] + B[c] )
#define S_BM 64
#define S_BK 16
template <bool RELU>
__global__ __launch_bounds__(256)
void sage_kernel(const float* __restrict__ X_in,
                 const float* __restrict__ Wl,
                 const float* __restrict__ Wr,
                 const float* __restrict__ B,
                 float* __restrict__ OUT_in,
                 int N) {
    const float* X = X_in ? X_in : g_h;
    float* OUT     = OUT_in ? OUT_in : g_h;

    __shared__ float sAx[S_BM][S_BK];
    __shared__ float sAm[S_BM][S_BK];
    __shared__ float sBl[S_BK][128];
    __shared__ float sBr[S_BK][128];

    const int tid = threadIdx.x;
    const int tx  = tid & 31;
    const int ty  = tid >> 5;
    const int bm  = blockIdx.x * S_BM;

    float acc[8][4];
#pragma unroll
    for (int i = 0; i < 8; i++)
#pragma unroll
        for (int j = 0; j < 4; j++) acc[i][j] = 0.f;

    for (int kc = 0; kc < DD; kc += S_BK) {
#pragma unroll
        for (int i = 0; i < 4; i++) {
            int idx = tid + i * 256;
            int r = idx >> 4, c = idx & 15;
            int n = bm + r;
            float vx = 0.f, vm = 0.f;
            if (n < N) {
                vx = X[(size_t)n * DD + kc + c];
                vm = g_msg[(size_t)n * DD + kc + c];
            }
            sAx[r][c] = vx;
            sAm[r][c] = vm;
        }
#pragma unroll
        for (int i = 0; i < 8; i++) {
            int idx = tid + i * 256;
            int kk = idx >> 7, c = idx & 127;
            sBl[kk][c] = Wl[(size_t)(kc + kk) * 128 + c];
            sBr[kk][c] = Wr[(size_t)(kc + kk) * 128 + c];
        }
        __syncthreads();

#pragma unroll
        for (int kk = 0; kk < S_BK; kk++) {
            float4 bl = *reinterpret_cast<const float4*>(&sBl[kk][tx * 4]);
            float4 br = *reinterpret_cast<const float4*>(&sBr[kk][tx * 4]);
#pragma unroll
            for (int i = 0; i < 8; i++) {
                float am = sAm[ty * 8 + i][kk];
                float ax = sAx[ty * 8 + i][kk];
                acc[i][0] += am * bl.x + ax * br.x;
                acc[i][1] += am * bl.y + ax * br.y;
                acc[i][2] += am * bl.z + ax * br.z;
                acc[i][3] += am * bl.w + ax * br.w;
            }
        }
        __syncthreads();
    }

    float4 bias = *reinterpret_cast<const float4*>(&B[tx * 4]);
#pragma unroll
    for (int i = 0; i < 8; i++) {
        int n = bm + ty * 8 + i;
        if (n < N) {
            float4 o;
            o.x = acc[i][0] + bias.x;
            o.y = acc[i][1] + bias.y;
            o.z = acc[i][2] + bias.z;
            o.w = acc[i][3] + bias.w;
            if (RELU) {
                o.x = fmaxf(o.x, 0.f); o.y = fmaxf(o.y, 0.f);
                o.z = fmaxf(o.z, 0.f); o.w = fmaxf(o.w, 0.f);
            }
            *reinterpret_cast<float4*>(&OUT[(size_t)n * DD + tx * 4]) = o;
        }
    }
}

// ---------------- fused MLP + pred ----------------
// h1 = relu( relu(EMB) @ Wm1 + bm1 );  PRED[n] = h1[n] . Wm2 + bm2
#define M_BM 32
#define M_BK 32
__global__ __launch_bounds__(256)
void mlp_pred_kernel(const float* __restrict__ EMB,
                     const float* __restrict__ Wm1,
                     const float* __restrict__ bm1,
                     const float* __restrict__ Wm2,
                     const float* __restrict__ bm2,
                     float* __restrict__ PRED,
                     int N) {
    __shared__ float sA[M_BM][M_BK];
    __shared__ float sB[M_BK][256];
    __shared__ float sred[M_BM][65];

    const int tid = threadIdx.x;
    const int tx  = tid & 63;
    const int ty  = tid >> 6;
    const int bm  = blockIdx.x * M_BM;

    float acc[8][4];
#pragma unroll
    for (int i = 0; i < 8; i++)
#pragma unroll
        for (int j = 0; j < 4; j++) acc[i][j] = 0.f;

    for (int kc = 0; kc < DD; kc += M_BK) {
#pragma unroll
        for (int i = 0; i < 4; i++) {
            int idx = tid + i * 256;
            int r = idx >> 5, c = idx & 31;
            int n = bm + r;
            sA[r][c] = (n < N) ? fmaxf(EMB[(size_t)n * DD + kc + c], 0.f) : 0.f;
        }
#pragma unroll
        for (int i = 0; i < 32; i++) {
            int idx = tid + i * 256;
            int kk = idx >> 8, c = idx & 255;
            sB[kk][c] = Wm1[(size_t)(kc + kk) * 256 + c];
        }
        __syncthreads();

#pragma unroll
        for (int kk = 0; kk < M_BK; kk++) {
            float4 b4 = *reinterpret_cast<const float4*>(&sB[kk][tx * 4]);
#pragma unroll
            for (int i = 0; i < 8; i++) {
                float a = sA[ty * 8 + i][kk];
                acc[i][0] += a * b4.x;
                acc[i][1] += a * b4.y;
                acc[i][2] += a * b4.z;
                acc[i][3] += a * b4.w;
            }
        }
        __syncthreads();
    }

    float4 bias = *reinterpret_cast<const float4*>(&bm1[tx * 4]);
    float4 w2   = *reinterpret_cast<const float4*>(&Wm2[tx * 4]);
#pragma unroll
    for (int i = 0; i < 8; i++) {
        float h0 = fmaxf(acc[i][0] + bias.x, 0.f);
        float h1 = fmaxf(acc[i][1] + bias.y, 0.f);
        float h2 = fmaxf(acc[i][2] + bias.z, 0.f);
        float h3 = fmaxf(acc[i][3] + bias.w, 0.f);
        sred[ty * 8 + i][tx] = h0 * w2.x + h1 * w2.y + h2 * w2.z + h3 * w2.w;
    }
    __syncthreads();

    if (tid < M_BM) {
        int n = bm + tid;
        if (n < N) {
            float s = 0.f;
#pragma unroll
            for (int j = 0; j < 64; j++) s += sred[tid][j];
            PRED[n] = s + bm2[0];
        }
    }
}

// ---------------- launcher ----------------
extern "C" void kernel_launch(void* const* d_in, const int* in_sizes, int n_in,
                              void* d_out, int out_size) {
    const float* x   = (const float*)d_in[0];
    const void*  ei  = d_in[1];
    const float* Wl0 = (const float*)d_in[2];
    const float* b0  = (const float*)d_in[3];
    const float* Wr0 = (const float*)d_in[4];
    const float* Wl1 = (const float*)d_in[5];
    const float* b1  = (const float*)d_in[6];
    const float* Wr1 = (const float*)d_in[7];
    const float* Wm1 = (const float*)d_in[8];
    const float* bm1 = (const float*)d_in[9];
    const float* Wm2 = (const float*)d_in[10];
    const float* bm2 = (const float*)d_in[11];

    const int N = in_sizes[0] / DD;
    const int E = in_sizes[1] / 2;

    float* out  = (float*)d_out;
    float* emb  = out;                       // [N,128]
    float* pred = out + (size_t)N * DD;      // [N,1]

    const int egrid = (E + 255) / 256;
    const int ngrid = (N + 255) / 256;
    const int nblk  = (N + 1023) / 1024;
    const int ggrid = (N + 7) / 8;
    const int sgrid = (N + S_BM - 1) / S_BM;
    const int mgrid = (N + M_BM - 1) / M_BM;

    detect_kernel<<<1, 32>>>((const int*)ei);

    // ---- CSR build (once; reused by both layers) ----
    zero_hist_kernel<<<ngrid, 256>>>(N);
    hist_kernel<<<egrid, 256>>>(ei, E);
    scan1_kernel<<<nblk, 1024>>>(N);
    scan2_kernel<<<1, 32>>>(nblk);
    scan3_kernel<<<ngrid, 256>>>(N, E);
    scatter_kernel<<<egrid, 256>>>(ei, E);

    // ---- layer 0 ----
    gather_agg_kernel<<<ggrid, 256>>>(x, N);
    sage_kernel<true><<<sgrid, 256>>>(x, Wl0, Wr0, b0, nullptr, N);   // OUT -> g_h

    // ---- layer 1 (emb -> d_out) ----
    gather_agg_kernel<<<ggrid, 256>>>(nullptr, N);
    sage_kernel<false><<<sgrid, 256>>>(nullptr, Wl1, Wr1, b1, emb, N);

    // ---- post-mp MLP + pred (fused) ----
    mlp_pred_kernel<<<mgrid, 256>>>(emb, Wm1, bm1, Wm2, bm2, pred, N);
}